// round 5
// baseline (speedup 1.0000x reference)
#include <cuda_runtime.h>
#include <math.h>

#define NN 2048
#define TT 4096
#define MAX_SPIKES 256
#define ALPHA 0.01f
#define DT (1.0f/4096.0f)

// Output layout (floats), tuple order: ys, tevents, yevents, event_types, num_spikes
#define YS_LEN   ((size_t)TT * NN * 3)            // 25165824
#define TEV_OFF  (YS_LEN)                         // 25165824
#define YEV_OFF  (TEV_OFF + MAX_SPIKES)           // 25166080
#define YEV_LEN  ((size_t)MAX_SPIKES * NN * 3)    // 1572864
#define ET_OFF   (YEV_OFF + YEV_LEN)              // 26738944
#define ET_LEN   ((size_t)MAX_SPIKES * NN)        // 524288
#define NS_OFF   (ET_OFF + ET_LEN)                // 27263232

__global__ void init_tail_kernel(float* __restrict__ out) {
    const float INF = __int_as_float(0x7f800000);
    size_t total = (size_t)MAX_SPIKES + YEV_LEN + ET_LEN;
    size_t stride = (size_t)gridDim.x * blockDim.x;
    for (size_t i = (size_t)blockIdx.x * blockDim.x + threadIdx.x; i < total; i += stride) {
        out[TEV_OFF + i] = (i < (size_t)MAX_SPIKES + YEV_LEN) ? INF : 0.0f;
    }
}

__device__ __forceinline__ float softplus_f(float v) {
    // jnp.logaddexp(v, 0) = max(v,0) + log1p(exp(-|v|))  (libdevice expf/log1pf)
    return __fadd_rn(fmaxf(v, 0.0f), log1pf(expf(-fabsf(v))));
}

__global__ void __launch_bounds__(1024, 1)
snn_kernel(const float* __restrict__ w,
           const float* __restrict__ mu,
           const float* __restrict__ v0,
           const float* __restrict__ i0,
           const float* __restrict__ ic,
           const float* __restrict__ u_rs,
           const float* __restrict__ u_init,
           float* __restrict__ out) {
    __shared__ int eidx[3];
    const int tid = threadIdx.x;
    const int n0 = 2 * tid, n1 = n0 + 1;

    if (tid < 3) eidx[tid] = NN;

    const float mu1 = mu[0], mu2 = mu[1];
    float v_0 = v0[n0], v_1 = v0[n1];
    float ii0 = i0[n0], ii1 = i0[n1];
    float s_0 = __fsub_rn(logf(u_init[n0]), ALPHA);
    float s_1 = __fsub_rn(logf(u_init[n1]), ALPHA);
    int cnt = 0;

    // depth-2 prefetch: icv/uv = step t, icA/uA = step t+1
    float2 icv = *(const float2*)(ic + n0);
    float2 uv  = *(const float2*)(u_rs + n0);
    float2 icA = *(const float2*)(ic + NN + n0);
    float2 uA  = *(const float2*)(u_rs + NN + n0);
    __syncthreads();

    int b = 0;  // rotating reduction buffer index (t % 3)
    for (int t = 0; t < TT; ++t) {
        // ---- 1. intensity chain FIRST (depends only on v, s — the true serial chain)
        float sp0 = softplus_f(v_0), sp1 = softplus_f(v_1);
        float s1_0 = __fadd_rn(s_0, __fmul_rn(DT, sp0));
        float s1_1 = __fadd_rn(s_1, __fmul_rn(DT, sp1));
        bool m0 = (s1_0 >= 0.0f), m1 = (s1_1 >= 0.0f);

        if (m0)      atomicMin(&eidx[b], n0);
        else if (m1) atomicMin(&eidx[b], n1);

        // ---- 2. deferred ys store: state regs currently hold y_new of step t-1.
        //        Streaming (.cs) so the 96MB write stream doesn't evict w from L2.
        if (t > 0) {
            float* yrow = out + (size_t)(t - 1) * (NN * 3) + 6 * (size_t)tid;
            __stcs((float2*)(yrow),     make_float2(v_0, ii0));
            __stcs((float2*)(yrow + 2), make_float2(s_0, v_1));
            __stcs((float2*)(yrow + 4), make_float2(ii1, s_1));
        }

        // ---- 3. off-chain v/i update (exact reference op order, no contraction)
        float v1_0 = __fadd_rn(v_0, __fmul_rn(DT, __fmul_rn(mu1, __fsub_rn(__fadd_rn(ii0, icv.x), v_0))));
        float v1_1 = __fadd_rn(v_1, __fmul_rn(DT, __fmul_rn(mu1, __fsub_rn(__fadd_rn(ii1, icv.y), v_1))));
        float i1_0 = __fadd_rn(ii0, __fmul_rn(DT, __fmul_rn(-mu2, ii0)));
        float i1_1 = __fadd_rn(ii1, __fmul_rn(DT, __fmul_rn(-mu2, ii1)));

        // ---- 4. prefetch ic/u for step t+2 (2 steps of DRAM-latency slack)
        float2 icB = make_float2(0.0f, 0.0f), uB = make_float2(1.0f, 1.0f);
        if (t + 2 < TT) {
            icB = *(const float2*)(ic   + (size_t)(t + 2) * NN + n0);
            uB  = *(const float2*)(u_rs + (size_t)(t + 2) * NN + n0);
        }

        // ---- 5. barrier + fused OR-reduction (event flag for free)
        int event = __syncthreads_or((int)(m0 | m1));

        float w0 = 0.0f, w1 = 0.0f;
        if (event) {
            int e = eidx[b];
            float2 wr = *(const float2*)(w + (size_t)e * NN + n0);   // consumed next step
            w0 = wr.x; w1 = wr.y;
        }
        if (tid == 0) {
            int b2 = b + 2; if (b2 >= 3) b2 -= 3;
            eidx[b2] = NN;  // reset buffer for step t+2 (barrier-separated from its writers)
        }

        // ---- 6. commit state = y_new of step t
        float v2_0 = __fsub_rn(v1_0, m0 ? 1.0f : 0.0f);
        float v2_1 = __fsub_rn(v1_1, m1 ? 1.0f : 0.0f);
        float i2_0 = __fadd_rn(i1_0, w0);
        float i2_1 = __fadd_rn(i1_1, w1);
        float s2_0 = m0 ? __fsub_rn(logf(uv.x), ALPHA) : s1_0;
        float s2_1 = m1 ? __fsub_rn(logf(uv.y), ALPHA) : s1_1;

        // ---- 7. record event (rare: at most MAX_SPIKES event-steps get recorded)
        if (event && cnt < MAX_SPIKES) {
            if (tid == 0) out[TEV_OFF + cnt] = __fmul_rn((float)t + 1.0f, DT);
            float* ye = out + YEV_OFF + (size_t)cnt * (NN * 3) + 6 * (size_t)tid;
            __stcs((float2*)(ye),     make_float2(v1_0, i1_0));
            __stcs((float2*)(ye + 2), make_float2(s1_0, v1_1));
            __stcs((float2*)(ye + 4), make_float2(i1_1, s1_1));
            float* er = out + ET_OFF + (size_t)cnt * NN + n0;
            __stcs((float2*)(er), make_float2(m0 ? 1.0f : 0.0f, m1 ? 1.0f : 0.0f));
            cnt++;
        }

        v_0 = v2_0; v_1 = v2_1;
        ii0 = i2_0; ii1 = i2_1;
        s_0 = s2_0; s_1 = s2_1;

        icv = icA; icA = icB;
        uv  = uA;  uA  = uB;
        b = (b == 2) ? 0 : b + 1;
    }

    // final ys row (y_new of step T-1)
    {
        float* yrow = out + (size_t)(TT - 1) * (NN * 3) + 6 * (size_t)tid;
        __stcs((float2*)(yrow),     make_float2(v_0, ii0));
        __stcs((float2*)(yrow + 2), make_float2(s_0, v_1));
        __stcs((float2*)(yrow + 4), make_float2(ii1, s_1));
    }

    if (tid == 0) out[NS_OFF] = (float)cnt;
}

extern "C" void kernel_launch(void* const* d_in, const int* in_sizes, int n_in,
                              void* d_out, int out_size) {
    // metadata order: w, mu, v0, i0, ic, u_init, u_resample
    const float* w      = (const float*)d_in[0];
    const float* mu     = (const float*)d_in[1];
    const float* v0     = (const float*)d_in[2];
    const float* i0     = (const float*)d_in[3];
    const float* ic     = (const float*)d_in[4];
    const float* u_init = (const float*)d_in[5];
    const float* u_rs   = (const float*)d_in[6];
    float* out = (float*)d_out;

    init_tail_kernel<<<512, 256>>>(out);
    snn_kernel<<<1, 1024>>>(w, mu, v0, i0, ic, u_rs, u_init, out);
}

// round 7
// speedup vs baseline: 1.2743x; 1.2743x over previous
#include <cuda_runtime.h>
#include <math.h>
#include <cstdint>

#define NN 2048
#define TT 4096
#define MAX_SPIKES 256
#define ALPHA 0.01f
#define DT (1.0f/4096.0f)
#define CLUSTER 8
#define TPB 256   // 1 neuron per thread; 8 CTAs x 256 = 2048

// Output layout (floats), tuple order: ys, tevents, yevents, event_types, num_spikes
#define YS_LEN   ((size_t)TT * NN * 3)            // 25165824
#define TEV_OFF  (YS_LEN)                         // 25165824
#define YEV_OFF  (TEV_OFF + MAX_SPIKES)           // 25166080
#define YEV_LEN  ((size_t)MAX_SPIKES * NN * 3)    // 1572864
#define ET_OFF   (YEV_OFF + YEV_LEN)              // 26738944
#define ET_LEN   ((size_t)MAX_SPIKES * NN)        // 524288
#define NS_OFF   (ET_OFF + ET_LEN)                // 27263232

__global__ void init_tail_kernel(float* __restrict__ out) {
    const float INF = __int_as_float(0x7f800000);
    size_t total = (size_t)MAX_SPIKES + YEV_LEN + ET_LEN;
    size_t stride = (size_t)gridDim.x * blockDim.x;
    for (size_t i = (size_t)blockIdx.x * blockDim.x + threadIdx.x; i < total; i += stride) {
        out[TEV_OFF + i] = (i < (size_t)MAX_SPIKES + YEV_LEN) ? INF : 0.0f;
    }
}

__device__ __forceinline__ float softplus_f(float v) {
    // jnp.logaddexp(v, 0) = max(v,0) + log1p(exp(-|v|))  (libdevice expf/log1pf)
    return __fadd_rn(fmaxf(v, 0.0f), log1pf(expf(-fabsf(v))));
}

__device__ __forceinline__ uint32_t smem_u32(const void* p) {
    uint32_t a;
    asm("{ .reg .u64 t; cvta.to.shared.u64 t, %1; cvt.u32.u64 %0, t; }" : "=r"(a) : "l"(p));
    return a;
}

__device__ __forceinline__ uint32_t ctarank() {
    uint32_t r; asm("mov.u32 %0, %%cluster_ctarank;" : "=r"(r)); return r;
}

__device__ __forceinline__ void red_min_remote(uint32_t local_addr, uint32_t rank, int v) {
    uint32_t ra;
    asm volatile("mapa.shared::cluster.u32 %0, %1, %2;" : "=r"(ra) : "r"(local_addr), "r"(rank));
    asm volatile("red.relaxed.cluster.shared::cluster.min.s32 [%0], %1;" :: "r"(ra), "r"(v) : "memory");
}

#define CLUSTER_SYNC() do { \
    asm volatile("barrier.cluster.arrive.aligned;" ::: "memory"); \
    asm volatile("barrier.cluster.wait.aligned;" ::: "memory"); \
} while (0)

__global__ void __launch_bounds__(TPB, 1) __cluster_dims__(CLUSTER, 1, 1)
snn_kernel(const float* __restrict__ w,
           const float* __restrict__ mu,
           const float* __restrict__ v0,
           const float* __restrict__ i0,
           const float* __restrict__ ic,
           const float* __restrict__ u_rs,
           const float* __restrict__ u_init,
           float* __restrict__ out) {
    __shared__ int eidx[3];
    const int tid  = threadIdx.x;
    const int lane = tid & 31;
    const uint32_t rank = ctarank();
    const int n = (int)rank * TPB + tid;           // this thread's neuron
    const uint32_t eidx_base = smem_u32(eidx);

    if (tid < 3) eidx[tid] = NN;

    const float mu1 = mu[0], mu2 = mu[1];
    float v_  = v0[n];
    float ii  = i0[n];
    float s_  = __fsub_rn(logf(u_init[n]), ALPHA);
    int cnt = 0;

    // depth-2 prefetch of ic/u rows
    float icv = ic[n],        uvv = u_rs[n];
    float icA = ic[NN + n],   uA  = u_rs[NN + n];

    __syncthreads();
    CLUSTER_SYNC();   // all CTAs' eidx slots initialized before any remote red

    int b = 0;
    for (int t = 0; t < TT; ++t) {
        // ---- 1. serial chain: softplus -> s1 -> mask
        float sp  = softplus_f(v_);
        float s1  = __fadd_rn(s_, __fmul_rn(DT, sp));
        bool  m   = (s1 >= 0.0f);

        unsigned val  = m ? (unsigned)n : (unsigned)NN;
        unsigned wmin = __reduce_min_sync(0xffffffffu, val);
        if (lane == 0 && wmin < NN) atomicMin(&eidx[b], (int)wmin);

        // ---- 2. deferred ys store of step t-1 (regs hold committed y_new)
        if (t > 0) {
            float* yrow = out + (size_t)(t - 1) * (NN * 3) + 3 * (size_t)n;
            __stcs(yrow,     v_);
            __stcs(yrow + 1, ii);
            __stcs(yrow + 2, s_);
        }

        // ---- 3. off-chain v/i update (exact reference op order)
        float v1 = __fadd_rn(v_, __fmul_rn(DT, __fmul_rn(mu1, __fsub_rn(__fadd_rn(ii, icv), v_))));
        float i1 = __fadd_rn(ii, __fmul_rn(DT, __fmul_rn(-mu2, ii)));

        // ---- 4. prefetch ic/u for step t+2
        float icB = 0.0f, uB = 1.0f;
        if (t + 2 < TT) {
            icB = ic  [(size_t)(t + 2) * NN + n];
            uB  = u_rs[(size_t)(t + 2) * NN + n];
        }

        // ---- 5. local barrier, broadcast CTA-min to peers, cluster barrier
        __syncthreads();
        if (tid == 0) {
            int lmin = eidx[b];
            if (lmin < NN) {
                #pragma unroll
                for (uint32_t r = 0; r < CLUSTER; ++r)
                    if (r != rank) red_min_remote(eidx_base + 4u * b, r, lmin);
            }
            int b2 = b + 2; if (b2 >= 3) b2 -= 3;
            eidx[b2] = NN;   // reset slot for step t+2 (>=2 cluster barriers from writers/readers)
        }
        CLUSTER_SYNC();

        int e = eidx[b];          // global argmin (first masked neuron)
        bool event = (e < NN);

        // ---- 6. transition + commit (w row applied to ALL neurons on event)
        float wn = 0.0f;
        if (event) wn = w[(size_t)e * NN + n];

        float v2 = __fsub_rn(v1, m ? 1.0f : 0.0f);
        float i2 = __fadd_rn(i1, wn);
        float s2 = m ? __fsub_rn(logf(uvv), ALPHA) : s1;

        // ---- 7. record event (first MAX_SPIKES event-steps)
        if (event && cnt < MAX_SPIKES) {
            if (rank == 0 && tid == 0)
                out[TEV_OFF + cnt] = __fmul_rn((float)t + 1.0f, DT);
            float* ye = out + YEV_OFF + (size_t)cnt * (NN * 3) + 3 * (size_t)n;
            __stcs(ye,     v1);
            __stcs(ye + 1, i1);
            __stcs(ye + 2, s1);
            __stcs(out + ET_OFF + (size_t)cnt * NN + n, m ? 1.0f : 0.0f);
            cnt++;
        }

        v_ = v2; ii = i2; s_ = s2;
        icv = icA; icA = icB;
        uvv = uA;  uA  = uB;
        b = (b == 2) ? 0 : b + 1;
    }

    // final ys row (y_new of step T-1)
    {
        float* yrow = out + (size_t)(TT - 1) * (NN * 3) + 3 * (size_t)n;
        __stcs(yrow,     v_);
        __stcs(yrow + 1, ii);
        __stcs(yrow + 2, s_);
    }
    if (rank == 0 && tid == 0) out[NS_OFF] = (float)cnt;

    CLUSTER_SYNC();   // no CTA exits while peer reds may target its SMEM
}

extern "C" void kernel_launch(void* const* d_in, const int* in_sizes, int n_in,
                              void* d_out, int out_size) {
    // metadata order: w, mu, v0, i0, ic, u_init, u_resample
    const float* w      = (const float*)d_in[0];
    const float* mu     = (const float*)d_in[1];
    const float* v0     = (const float*)d_in[2];
    const float* i0     = (const float*)d_in[3];
    const float* ic     = (const float*)d_in[4];
    const float* u_init = (const float*)d_in[5];
    const float* u_rs   = (const float*)d_in[6];
    float* out = (float*)d_out;

    init_tail_kernel<<<512, 256>>>(out);
    snn_kernel<<<CLUSTER, TPB>>>(w, mu, v0, i0, ic, u_rs, u_init, out);
}